// round 2
// baseline (speedup 1.0000x reference)
#include <cuda_runtime.h>
#include <math.h>

#define D 1024
#define EXP 7
#define NTOK 8192
#define CAP 2574            // int(8192*2/7*1.1)
#define NSLOTS (EXP*CAP)    // 18018

// ---- scratch (static device globals; no allocation anywhere) ----
__device__ float g_Hs[NTOK * D];        // shared-expert hidden
__device__ float g_Hexp[NSLOTS * D];    // expert hidden
__device__ float g_Oexp[NSLOTS * D];    // expert output
__device__ int   g_slot_token[NSLOTS];  // token id per slot (sentinel = big)
__device__ int   g_slot_of[NTOK * 2];   // token -> slot per top-k choice (-1 = dropped)
__device__ int   g_top[NTOK];           // e0 | e1<<4
__device__ float g_gate0[NTOK];
__device__ float g_gate1[NTOK];
__device__ int   g_mask[NTOK];          // expert bitmask

// ======================= router =======================
__global__ void __launch_bounds__(256) router_kernel(
    const float* __restrict__ x, const float* __restrict__ noise,
    const float* __restrict__ Wr, const float* __restrict__ br,
    const float* __restrict__ Wn, const float* __restrict__ bn)
{
    int n = blockIdx.x;
    const float* xr = x + (size_t)n * D;
    float aR[EXP], aN[EXP];
#pragma unroll
    for (int e = 0; e < EXP; e++) { aR[e] = 0.f; aN[e] = 0.f; }
    for (int d = threadIdx.x; d < D; d += 256) {
        float xv = xr[d];
        const float* wr = Wr + d * EXP;
        const float* wn = Wn + d * EXP;
#pragma unroll
        for (int e = 0; e < EXP; e++) {
            aR[e] = fmaf(xv, wr[e], aR[e]);
            aN[e] = fmaf(xv, wn[e], aN[e]);
        }
    }
    __shared__ float wred[8][14];
    int lane = threadIdx.x & 31, warp = threadIdx.x >> 5;
#pragma unroll
    for (int i = 0; i < 14; i++) {
        float v = (i < EXP) ? aR[i] : aN[i - EXP];
#pragma unroll
        for (int o = 16; o > 0; o >>= 1) v += __shfl_down_sync(0xffffffffu, v, o);
        if (lane == 0) wred[warp][i] = v;
    }
    __syncthreads();
    if (threadIdx.x == 0) {
        float logit[EXP];
#pragma unroll
        for (int e = 0; e < EXP; e++) {
            float sR = 0.f, sN = 0.f;
#pragma unroll
            for (int w = 0; w < 8; w++) { sR += wred[w][e]; sN += wred[w][e + EXP]; }
            float z  = sN + bn[e];
            float sp = (z > 20.f) ? z : log1pf(expf(z));
            logit[e] = sR + br[e] + noise[(size_t)n * EXP + e] * sp;
        }
        int e0 = 0; float v0 = logit[0];
#pragma unroll
        for (int e = 1; e < EXP; e++) if (logit[e] > v0) { v0 = logit[e]; e0 = e; }
        int e1 = -1; float v1 = -INFINITY;
#pragma unroll
        for (int e = 0; e < EXP; e++) if (e != e0 && logit[e] > v1) { v1 = logit[e]; e1 = e; }
        float ex = expf(v1 - v0);
        float g0 = 1.f / (1.f + ex);
        float g1 = ex / (1.f + ex);
        g_top[n]   = e0 | (e1 << 4);
        g_gate0[n] = g0;
        g_gate1[n] = g1;
        g_mask[n]  = (1 << e0) | (1 << e1);
        g_slot_of[2 * n]     = -1;
        g_slot_of[2 * n + 1] = -1;
    }
}

// ======================= slot init =======================
__global__ void init_slots()
{
    int i = blockIdx.x * 256 + threadIdx.x;
    if (i < NSLOTS) g_slot_token[i] = 1 << 30;
}

// ======================= ordered capacity scan (single block) =======================
__global__ void __launch_bounds__(1024) scan_kernel(float* __restrict__ dout, int lbl_idx)
{
    __shared__ int   base[EXP];
    __shared__ float probsum[EXP];
    __shared__ int   cnt[EXP];
    __shared__ int   wcnt[32];
    __shared__ int   woff[32];
    __shared__ int   total_s;
    int tid = threadIdx.x, lane = tid & 31, warp = tid >> 5;
    if (tid < EXP) { base[tid] = 0; probsum[tid] = 0.f; cnt[tid] = 0; }
    __syncthreads();

    for (int tile = 0; tile < NTOK / 1024; tile++) {
        int n  = tile * 1024 + tid;
        int mk = g_mask[n];
        int tp = g_top[n];
        int e0 = tp & 15, e1 = (tp >> 4) & 15;
        float g0 = g_gate0[n], g1 = g_gate1[n];
        atomicAdd(&probsum[e0], g0);
        atomicAdd(&probsum[e1], g1);
        atomicAdd(&cnt[e0], 1);
        atomicAdd(&cnt[e1], 1);
#pragma unroll
        for (int e = 0; e < EXP; e++) {
            int flag = (mk >> e) & 1;
            unsigned bal = __ballot_sync(0xffffffffu, flag != 0);
            if (lane == 0) wcnt[warp] = __popc(bal);
            __syncthreads();
            if (warp == 0) {
                int v = wcnt[lane];
                int inc = v;
#pragma unroll
                for (int o = 1; o < 32; o <<= 1) {
                    int t = __shfl_up_sync(0xffffffffu, inc, o);
                    if (lane >= o) inc += t;
                }
                woff[lane] = inc - v;
                if (lane == 31) total_s = inc;
            }
            __syncthreads();
            if (flag) {
                int pos = base[e] + woff[warp] + __popc(bal & ((1u << lane) - 1u));
                if (pos < CAP) {
                    int slot = e * CAP + pos;
                    g_slot_token[slot] = n;
                    int k = (e == e0) ? 0 : 1;
                    g_slot_of[2 * n + k] = slot;
                }
            }
            __syncthreads();
            if (tid == 0) base[e] += total_s;
            __syncthreads();
        }
    }
    if (tid == 0) {
        float s = 0.f;
#pragma unroll
        for (int e = 0; e < EXP; e++)
            s += (probsum[e] / (float)NTOK) * ((float)cnt[e] / (float)NTOK);
        dout[lbl_idx] = (float)EXP * s;
    }
}

// ======================= SGEMM 128x128x8, 256 thr, 8x8 microtile =======================
// MODE 0: shared FFN1: A=x       -> relu -> g_Hs
// MODE 1: shared FFN2: A=g_Hs    ->       d_out
// MODE 2: expert FFN1: A=gather(x, slot_token) -> relu -> g_Hexp   (grid.z = EXP)
// MODE 3: expert FFN2: A=g_Hexp  ->       g_Oexp                   (grid.z = EXP)
template <int MODE>
__global__ void __launch_bounds__(256) sgemm_kernel(
    const float* __restrict__ A, const float* __restrict__ W,
    const float* __restrict__ bias, float* __restrict__ Out, int M)
{
    constexpr bool GATHER = (MODE == 2);
    constexpr bool RELU   = (MODE == 0 || MODE == 2);
    int z = blockIdx.z;
    const float* Wz = W + (size_t)z * D * D;
    const float* bz = bias + (size_t)z * D;
    const int* rowmap = nullptr;
    if constexpr (MODE == 0) { Out = g_Hs; }
    if constexpr (MODE == 1) { A = g_Hs; }
    if constexpr (MODE == 2) { rowmap = g_slot_token + z * CAP; Out = g_Hexp + (size_t)z * CAP * D; }
    if constexpr (MODE == 3) { A = g_Hexp + (size_t)z * CAP * D; Out = g_Oexp + (size_t)z * CAP * D; }

    __shared__ float As[8][128];
    __shared__ float Bs[8][128];

    int tid = threadIdx.x;
    int rowTile = blockIdx.y, colTile = blockIdx.x;

    int ar = tid >> 1;            // 0..127 (row within tile)
    int ak = (tid & 1) * 4;       // 0 or 4 (k offset)
    int gr = rowTile * 128 + ar;
    bool avalid;
    int  arow;
    if constexpr (GATHER) {
        int t = (gr < M) ? rowmap[gr] : (1 << 30);
        avalid = ((unsigned)t < (unsigned)NTOK);
        arow = avalid ? t : 0;
    } else {
        avalid = (gr < M);
        arow = avalid ? gr : 0;
    }
    const float* Arow = A + (size_t)arow * D;

    int bk = tid >> 5;            // 0..7
    int bc = (tid & 31) * 4;      // 0..124

    int ty = tid >> 4, tx = tid & 15;
    float acc[8][8];
#pragma unroll
    for (int i = 0; i < 8; i++)
#pragma unroll
        for (int j = 0; j < 8; j++) acc[i][j] = 0.f;

    for (int k0 = 0; k0 < D; k0 += 8) {
        float4 av = make_float4(0.f, 0.f, 0.f, 0.f);
        if (avalid) av = *(const float4*)(Arow + k0 + ak);
        As[ak + 0][ar] = av.x;
        As[ak + 1][ar] = av.y;
        As[ak + 2][ar] = av.z;
        As[ak + 3][ar] = av.w;
        float4 bv = *(const float4*)(Wz + (size_t)(k0 + bk) * D + colTile * 128 + bc);
        *(float4*)&Bs[bk][bc] = bv;
        __syncthreads();
#pragma unroll
        for (int kk = 0; kk < 8; kk++) {
            float a[8], b[8];
            *(float4*)&a[0] = *(const float4*)&As[kk][ty * 8];
            *(float4*)&a[4] = *(const float4*)&As[kk][ty * 8 + 4];
            *(float4*)&b[0] = *(const float4*)&Bs[kk][tx * 8];
            *(float4*)&b[4] = *(const float4*)&Bs[kk][tx * 8 + 4];
#pragma unroll
            for (int i = 0; i < 8; i++)
#pragma unroll
                for (int j = 0; j < 8; j++)
                    acc[i][j] = fmaf(a[i], b[j], acc[i][j]);
        }
        __syncthreads();
    }

    int n0 = colTile * 128 + tx * 8;
    float bb[8];
#pragma unroll
    for (int j = 0; j < 8; j++) bb[j] = bz[n0 + j];
#pragma unroll
    for (int i = 0; i < 8; i++) {
        int m = rowTile * 128 + ty * 8 + i;
        if (m < M) {
            float v[8];
#pragma unroll
            for (int j = 0; j < 8; j++) {
                v[j] = acc[i][j] + bb[j];
                if (RELU) v[j] = fmaxf(v[j], 0.f);
            }
            float* orow = Out + (size_t)m * D + n0;
            *(float4*)(orow)     = *(float4*)&v[0];
            *(float4*)(orow + 4) = *(float4*)&v[4];
        }
    }
}

// ======================= combine =======================
__global__ void __launch_bounds__(256) combine_kernel(float* __restrict__ out)
{
    int n = blockIdx.x;
    int s0 = g_slot_of[2 * n], s1 = g_slot_of[2 * n + 1];
    float g0 = g_gate0[n], g1 = g_gate1[n];
    float4* orow = (float4*)(out + (size_t)n * D);
    float4 v = orow[threadIdx.x];
    if (s0 >= 0) {
        float4 e = ((const float4*)(g_Oexp + (size_t)s0 * D))[threadIdx.x];
        v.x += g0 * e.x; v.y += g0 * e.y; v.z += g0 * e.z; v.w += g0 * e.w;
    }
    if (s1 >= 0) {
        float4 e = ((const float4*)(g_Oexp + (size_t)s1 * D))[threadIdx.x];
        v.x += g1 * e.x; v.y += g1 * e.y; v.z += g1 * e.z; v.w += g1 * e.w;
    }
    orow[threadIdx.x] = v;
}

// ======================= launch =======================
extern "C" void kernel_launch(void* const* d_in, const int* in_sizes, int n_in,
                              void* d_out, int out_size)
{
    const float* x     = (const float*)d_in[0];
    const float* noise = (const float*)d_in[1];
    const float* Wr    = (const float*)d_in[2];
    const float* br    = (const float*)d_in[3];
    const float* Wn    = (const float*)d_in[4];
    const float* bn    = (const float*)d_in[5];
    const float* W1    = (const float*)d_in[6];
    const float* b1    = (const float*)d_in[7];
    const float* W2    = (const float*)d_in[8];
    const float* b2    = (const float*)d_in[9];
    const float* Ws1   = (const float*)d_in[10];
    const float* bs1   = (const float*)d_in[11];
    const float* Ws2   = (const float*)d_in[12];
    const float* bs2   = (const float*)d_in[13];
    float* out = (float*)d_out;

    router_kernel<<<NTOK, 256>>>(x, noise, Wr, br, Wn, bn);
    init_slots<<<(NSLOTS + 255) / 256, 256>>>();
    scan_kernel<<<1, 1024>>>(out, out_size - 1);

    // shared expert
    sgemm_kernel<0><<<dim3(D / 128, NTOK / 128, 1), 256>>>(x, Ws1, bs1, nullptr, NTOK);
    sgemm_kernel<1><<<dim3(D / 128, NTOK / 128, 1), 256>>>(nullptr, Ws2, bs2, out, NTOK);

    // routed experts (21 row tiles covers CAP=2574)
    sgemm_kernel<2><<<dim3(D / 128, (CAP + 127) / 128, EXP), 256>>>(x, W1, b1, nullptr, CAP);
    sgemm_kernel<3><<<dim3(D / 128, (CAP + 127) / 128, EXP), 256>>>(nullptr, W2, b2, nullptr, CAP);

    combine_kernel<<<NTOK, 256>>>(out);
}

// round 5
// speedup vs baseline: 2.7138x; 2.7138x over previous
#include <cuda_runtime.h>
#include <cuda_bf16.h>
#include <math.h>
#include <stdint.h>

#define D 1024
#define EXP 7
#define NTOK 8192
#define CAP 2574            // int(8192*2/7*1.1)
#define NSLOTS (EXP*CAP)    // 18018

// ======================= device scratch (no runtime allocation) =======================
// NOTE: these are referenced ONLY from device code (never as host-side kernel args) —
// host-side symbol addresses of __device__ vars are invalid (and silently "work" via ATS on GB300).
__device__ alignas(16) __nv_bfloat16 g_x_hi[NTOK * D],  g_x_lo[NTOK * D];
__device__ alignas(16) __nv_bfloat16 g_Hs_hi[NTOK * D], g_Hs_lo[NTOK * D];
__device__ alignas(16) __nv_bfloat16 g_He_hi[NSLOTS * D], g_He_lo[NSLOTS * D];
__device__ alignas(16) __nv_bfloat16 g_W1t_hi[EXP * D * D], g_W1t_lo[EXP * D * D];
__device__ alignas(16) __nv_bfloat16 g_W2t_hi[EXP * D * D], g_W2t_lo[EXP * D * D];
__device__ alignas(16) __nv_bfloat16 g_Ws1t_hi[D * D], g_Ws1t_lo[D * D];
__device__ alignas(16) __nv_bfloat16 g_Ws2t_hi[D * D], g_Ws2t_lo[D * D];
__device__ alignas(16) float g_Oexp[NSLOTS * D];
__device__ int   g_slot_token[NSLOTS];
__device__ int   g_slot_of[NTOK * 2];
__device__ int   g_top[NTOK];
__device__ float g_gate0[NTOK];
__device__ float g_gate1[NTOK];
__device__ int   g_mask[NTOK];

// ======================= helpers (base ISA only: sm_80+) =======================
__device__ __forceinline__ uint32_t smem_to_u32(const void* p) {
    uint32_t a;
    asm("{ .reg .u64 t; cvta.to.shared.u64 t, %1; cvt.u32.u64 %0, t; }" : "=r"(a) : "l"(p));
    return a;
}
__device__ __forceinline__ void ldsm4(uint32_t& r0, uint32_t& r1, uint32_t& r2, uint32_t& r3,
                                      uint32_t addr) {
    asm volatile("ldmatrix.sync.aligned.m8n8.x4.shared.b16 {%0,%1,%2,%3}, [%4];"
                 : "=r"(r0), "=r"(r1), "=r"(r2), "=r"(r3) : "r"(addr));
}
__device__ __forceinline__ void mma16816(float* d, const uint32_t* a, const uint32_t* b) {
    asm volatile(
        "mma.sync.aligned.m16n8k16.row.col.f32.bf16.bf16.f32 "
        "{%0,%1,%2,%3}, {%4,%5,%6,%7}, {%8,%9}, {%0,%1,%2,%3};"
        : "+f"(d[0]), "+f"(d[1]), "+f"(d[2]), "+f"(d[3])
        : "r"(a[0]), "r"(a[1]), "r"(a[2]), "r"(a[3]), "r"(b[0]), "r"(b[1]));
}
__device__ __forceinline__ void cp_async16(uint32_t dst, const void* src, int src_size) {
    asm volatile("cp.async.cg.shared.global [%0], [%1], 16, %2;"
                 :: "r"(dst), "l"(src), "r"(src_size) : "memory");
}
#define CP_COMMIT() asm volatile("cp.async.commit_group;" ::: "memory")
#define CP_WAIT1()  asm volatile("cp.async.wait_group 1;" ::: "memory")

// ======================= router =======================
__global__ void __launch_bounds__(256) router_kernel(
    const float* __restrict__ x, const float* __restrict__ noise,
    const float* __restrict__ Wr, const float* __restrict__ br,
    const float* __restrict__ Wn, const float* __restrict__ bn)
{
    int n = blockIdx.x;
    const float* xr = x + (size_t)n * D;
    float aR[EXP], aN[EXP];
#pragma unroll
    for (int e = 0; e < EXP; e++) { aR[e] = 0.f; aN[e] = 0.f; }
    for (int d = threadIdx.x; d < D; d += 256) {
        float xv = xr[d];
        const float* wr = Wr + d * EXP;
        const float* wn = Wn + d * EXP;
#pragma unroll
        for (int e = 0; e < EXP; e++) {
            aR[e] = fmaf(xv, wr[e], aR[e]);
            aN[e] = fmaf(xv, wn[e], aN[e]);
        }
    }
    __shared__ float wred[8][14];
    int lane = threadIdx.x & 31, warp = threadIdx.x >> 5;
#pragma unroll
    for (int i = 0; i < 14; i++) {
        float v = (i < EXP) ? aR[i] : aN[i - EXP];
#pragma unroll
        for (int o = 16; o > 0; o >>= 1) v += __shfl_down_sync(0xffffffffu, v, o);
        if (lane == 0) wred[warp][i] = v;
    }
    __syncthreads();
    if (threadIdx.x == 0) {
        float logit[EXP];
#pragma unroll
        for (int e = 0; e < EXP; e++) {
            float sR = 0.f, sN = 0.f;
#pragma unroll
            for (int w = 0; w < 8; w++) { sR += wred[w][e]; sN += wred[w][e + EXP]; }
            float z  = sN + bn[e];
            float sp = (z > 20.f) ? z : log1pf(expf(z));
            logit[e] = sR + br[e] + noise[(size_t)n * EXP + e] * sp;
        }
        int e0 = 0; float v0 = logit[0];
#pragma unroll
        for (int e = 1; e < EXP; e++) if (logit[e] > v0) { v0 = logit[e]; e0 = e; }
        int e1 = -1; float v1 = -INFINITY;
#pragma unroll
        for (int e = 0; e < EXP; e++) if (e != e0 && logit[e] > v1) { v1 = logit[e]; e1 = e; }
        float ex = expf(v1 - v0);
        g_top[n]   = e0 | (e1 << 4);
        g_gate0[n] = 1.f / (1.f + ex);
        g_gate1[n] = ex / (1.f + ex);
        g_mask[n]  = (1 << e0) | (1 << e1);
        g_slot_of[2 * n]     = -1;
        g_slot_of[2 * n + 1] = -1;
    }
}

// ======================= slot init =======================
__global__ void init_slots()
{
    int i = blockIdx.x * 256 + threadIdx.x;
    if (i < NSLOTS) g_slot_token[i] = 1 << 30;
}

// ======================= ordered capacity scan (single block) =======================
__global__ void __launch_bounds__(1024) scan_kernel(float* __restrict__ dout, int lbl_idx)
{
    __shared__ int   base[EXP];
    __shared__ float probsum[EXP];
    __shared__ int   cnt[EXP];
    __shared__ int   wcnt[32];
    __shared__ int   woff[32];
    __shared__ int   total_s;
    int tid = threadIdx.x, lane = tid & 31, warp = tid >> 5;
    if (tid < EXP) { base[tid] = 0; probsum[tid] = 0.f; cnt[tid] = 0; }
    __syncthreads();

    for (int tile = 0; tile < NTOK / 1024; tile++) {
        int n  = tile * 1024 + tid;
        int mk = g_mask[n];
        int tp = g_top[n];
        int e0 = tp & 15, e1 = (tp >> 4) & 15;
        atomicAdd(&probsum[e0], g_gate0[n]);
        atomicAdd(&probsum[e1], g_gate1[n]);
        atomicAdd(&cnt[e0], 1);
        atomicAdd(&cnt[e1], 1);
#pragma unroll
        for (int e = 0; e < EXP; e++) {
            int flag = (mk >> e) & 1;
            unsigned bal = __ballot_sync(0xffffffffu, flag != 0);
            if (lane == 0) wcnt[warp] = __popc(bal);
            __syncthreads();
            if (warp == 0) {
                int v = wcnt[lane];
                int inc = v;
#pragma unroll
                for (int o = 1; o < 32; o <<= 1) {
                    int t = __shfl_up_sync(0xffffffffu, inc, o);
                    if (lane >= o) inc += t;
                }
                woff[lane] = inc - v;
                if (lane == 31) total_s = inc;
            }
            __syncthreads();
            if (flag) {
                int pos = base[e] + woff[warp] + __popc(bal & ((1u << lane) - 1u));
                if (pos < CAP) {
                    int slot = e * CAP + pos;
                    g_slot_token[slot] = n;
                    int k = (e == e0) ? 0 : 1;
                    g_slot_of[2 * n + k] = slot;
                }
            }
            __syncthreads();
            if (tid == 0) base[e] += total_s;
            __syncthreads();
        }
    }
    if (tid == 0) {
        float s = 0.f;
#pragma unroll
        for (int e = 0; e < EXP; e++)
            s += (probsum[e] / (float)NTOK) * ((float)cnt[e] / (float)NTOK);
        dout[lbl_idx] = (float)EXP * s;
    }
}

// ======================= split / transpose prep =======================
__global__ void __launch_bounds__(256) split_x_kernel(const float* __restrict__ x)
{
    int i = blockIdx.x * 256 + threadIdx.x;
    if (i < NTOK * D) {
        float v = x[i];
        __nv_bfloat16 h = __float2bfloat16(v);
        g_x_hi[i] = h;
        g_x_lo[i] = __float2bfloat16(v - __bfloat162float(h));
    }
}

// W[m][k][n] fp32 -> Wt[m][n][k] bf16 hi/lo. Destination selected by template (device symbols).
// WSEL: 0=Ws1t 1=Ws2t 2=W1t 3=W2t.  block (32,8), grid (32,32,nmats)
template <int WSEL>
__global__ void __launch_bounds__(256) wsplit_kernel(const float* __restrict__ W)
{
    __nv_bfloat16* hi; __nv_bfloat16* lo;
    if constexpr (WSEL == 0) { hi = g_Ws1t_hi; lo = g_Ws1t_lo; }
    if constexpr (WSEL == 1) { hi = g_Ws2t_hi; lo = g_Ws2t_lo; }
    if constexpr (WSEL == 2) { hi = g_W1t_hi;  lo = g_W1t_lo;  }
    if constexpr (WSEL == 3) { hi = g_W2t_hi;  lo = g_W2t_lo;  }
    __shared__ float t[32][33];
    int m = blockIdx.z;
    const float* Wm = W + (size_t)m * D * D;
    int n0 = blockIdx.x * 32, k0 = blockIdx.y * 32;
    int tx = threadIdx.x, ty = threadIdx.y;
#pragma unroll
    for (int r = 0; r < 4; r++) {
        int k = k0 + ty + r * 8;
        t[ty + r * 8][tx] = Wm[(size_t)k * D + n0 + tx];
    }
    __syncthreads();
#pragma unroll
    for (int r = 0; r < 4; r++) {
        int n = n0 + ty + r * 8;
        int k = k0 + tx;
        float v = t[tx][ty + r * 8];
        __nv_bfloat16 h = __float2bfloat16(v);
        size_t o = (size_t)m * D * D + (size_t)n * D + k;
        hi[o] = h;
        lo[o] = __float2bfloat16(v - __bfloat162float(h));
    }
}

// ======================= HMMA bf16x2-split GEMM =======================
// Block 128x128, K' = 3*1024 in 48 chunks of 64. cp.async double buffer.
// Warp grid 2(M) x 4(N); warp tile 64x32; mma.m16n8k16.
// All scratch operands bound via device symbols inside the kernel (MODE dispatch).
// MODE 0: shared FFN1  A=x(split)        B=Ws1t  relu -> Hs(split)
// MODE 1: shared FFN2  A=Hs(split)       B=Ws2t       -> OutF param (d_out)
// MODE 2: expert FFN1  A=gather x(split) B=W1t[z] relu-> He(split)   grid.z=EXP
// MODE 3: expert FFN2  A=He(split)       B=W2t[z]     -> g_Oexp      grid.z=EXP
#define NCHUNK 48
#define STAGE_BYTES 32768            // A 16KB + B 16KB
#define GEMM_SMEM (2 * STAGE_BYTES + 1024)

template <int MODE>
__global__ void __launch_bounds__(256) moe_gemm(
    const float* __restrict__ bias, float* __restrict__ OutF, int M)
{
    constexpr bool GATHER = (MODE == 2);
    constexpr bool RELU   = (MODE == 0 || MODE == 2);
    extern __shared__ char smem[];
    uint32_t smem_base = smem_to_u32(smem);
    int tid = threadIdx.x, wid = tid >> 5, lane = tid & 31;
    int colTile = blockIdx.x, rowTile = blockIdx.y, z = blockIdx.z;
    int wm = wid & 1, wn = wid >> 1;          // 2 x 4 warp grid

    const __nv_bfloat16 *Ahi, *Alo, *Bhi, *Blo;
    __nv_bfloat16 *OutHi = nullptr, *OutLo = nullptr;
    if constexpr (MODE == 0) {
        Ahi = g_x_hi;  Alo = g_x_lo;  Bhi = g_Ws1t_hi; Blo = g_Ws1t_lo;
        OutHi = g_Hs_hi; OutLo = g_Hs_lo;
    }
    if constexpr (MODE == 1) {
        Ahi = g_Hs_hi; Alo = g_Hs_lo; Bhi = g_Ws2t_hi; Blo = g_Ws2t_lo;
    }
    if constexpr (MODE == 2) {
        Ahi = g_x_hi;  Alo = g_x_lo;
        Bhi = g_W1t_hi + (size_t)z * D * D; Blo = g_W1t_lo + (size_t)z * D * D;
        bias += (size_t)z * D;
        OutHi = g_He_hi + (size_t)z * CAP * D; OutLo = g_He_lo + (size_t)z * CAP * D;
    }
    if constexpr (MODE == 3) {
        Ahi = g_He_hi + (size_t)z * CAP * D; Alo = g_He_lo + (size_t)z * CAP * D;
        Bhi = g_W2t_hi + (size_t)z * D * D;  Blo = g_W2t_lo + (size_t)z * D * D;
        bias += (size_t)z * D;
        OutF = g_Oexp + (size_t)z * CAP * D;
    }

    int* s_rowsrc = (int*)(smem + 2 * STAGE_BYTES);
    if (tid < 128) {
        int gr = rowTile * 128 + tid;
        int src;
        if constexpr (GATHER) {
            int t = (gr < M) ? g_slot_token[z * CAP + gr] : (1 << 30);
            src = ((unsigned)t < (unsigned)NTOK) ? t : -1;
        } else {
            src = (gr < M) ? gr : -1;
        }
        s_rowsrc[tid] = src;
    }
    __syncthreads();

    // ---- stage loader: chunk c into buffer buf ----
    auto load_stage = [&](int c, int buf) {
        int seg = c >> 4;                       // 0: hiA*hiB  1: loA*hiB  2: hiA*loB
        int kb  = (c & 15) * 64;
        const __nv_bfloat16* aseg = (seg == 1) ? Alo : Ahi;
        const __nv_bfloat16* bseg = (seg == 2) ? Blo : Bhi;
        uint32_t abase = smem_base + buf * STAGE_BYTES;
        uint32_t bbase = abase + 16384;
#pragma unroll
        for (int i = 0; i < 4; i++) {
            int chunk = i * 256 + tid;
            int row = chunk >> 3, c0 = chunk & 7;
            uint32_t swc = (uint32_t)(c0 ^ (row & 7));
            int src = s_rowsrc[row];
            const void* ap = aseg + (size_t)(src < 0 ? 0 : src) * D + kb + c0 * 8;
            cp_async16(abase + row * 128 + swc * 16, ap, src < 0 ? 0 : 16);
            int n = colTile * 128 + row;
            cp_async16(bbase + row * 128 + swc * 16,
                       bseg + (size_t)n * D + kb + c0 * 8, 16);
        }
    };

    float acc[4][4][4];
#pragma unroll
    for (int mi = 0; mi < 4; mi++)
#pragma unroll
        for (int ni = 0; ni < 4; ni++)
#pragma unroll
            for (int q = 0; q < 4; q++) acc[mi][ni][q] = 0.f;

    load_stage(0, 0); CP_COMMIT();
    load_stage(1, 1); CP_COMMIT();

    for (int c = 0; c < NCHUNK; c++) {
        int buf = c & 1;
        CP_WAIT1();
        __syncthreads();
        uint32_t abase = smem_base + buf * STAGE_BYTES;
        uint32_t bbase = abase + 16384;
#pragma unroll
        for (int s = 0; s < 4; s++) {
            uint32_t afr[4][4], bfr[4][2];
#pragma unroll
            for (int mi = 0; mi < 4; mi++) {
                int row = wm * 64 + mi * 16 + (lane & 15);
                int kc  = s * 2 + (lane >> 4);
                uint32_t addr = abase + row * 128 + (uint32_t)((kc ^ (row & 7)) << 4);
                ldsm4(afr[mi][0], afr[mi][1], afr[mi][2], afr[mi][3], addr);
            }
#pragma unroll
            for (int nb = 0; nb < 2; nb++) {
                int row = wn * 32 + nb * 16 + ((lane >> 4) & 1) * 8 + (lane & 7);
                int kc  = s * 2 + ((lane >> 3) & 1);
                uint32_t addr = bbase + row * 128 + (uint32_t)((kc ^ (row & 7)) << 4);
                uint32_t q0, q1, q2, q3;
                ldsm4(q0, q1, q2, q3, addr);
                bfr[nb * 2][0] = q0;  bfr[nb * 2][1] = q1;
                bfr[nb * 2 + 1][0] = q2; bfr[nb * 2 + 1][1] = q3;
            }
#pragma unroll
            for (int mi = 0; mi < 4; mi++)
#pragma unroll
                for (int ni = 0; ni < 4; ni++)
                    mma16816(acc[mi][ni], afr[mi], bfr[ni]);
        }
        __syncthreads();
        if (c + 2 < NCHUNK) load_stage(c + 2, buf);
        CP_COMMIT();
    }

    // ---- epilogue ----
    int rbase = rowTile * 128 + wm * 64 + (lane >> 2);
    int cbase = colTile * 128 + wn * 32 + (lane & 3) * 2;
#pragma unroll
    for (int mi = 0; mi < 4; mi++) {
#pragma unroll
        for (int ni = 0; ni < 4; ni++) {
            int cc = cbase + ni * 8;
            float b0 = bias[cc], b1 = bias[cc + 1];
            float v00 = acc[mi][ni][0] + b0, v01 = acc[mi][ni][1] + b1;
            float v10 = acc[mi][ni][2] + b0, v11 = acc[mi][ni][3] + b1;
            int r0 = rbase + mi * 16, r1 = r0 + 8;
            if constexpr (RELU) {
                v00 = fmaxf(v00, 0.f); v01 = fmaxf(v01, 0.f);
                v10 = fmaxf(v10, 0.f); v11 = fmaxf(v11, 0.f);
                if (r0 < M) {
                    __nv_bfloat162 h = __floats2bfloat162_rn(v00, v01);
                    __nv_bfloat162 l = __floats2bfloat162_rn(
                        v00 - __bfloat162float(__low2bfloat16(h)),
                        v01 - __bfloat162float(__high2bfloat16(h)));
                    *(__nv_bfloat162*)(OutHi + (size_t)r0 * D + cc) = h;
                    *(__nv_bfloat162*)(OutLo + (size_t)r0 * D + cc) = l;
                }
                if (r1 < M) {
                    __nv_bfloat162 h = __floats2bfloat162_rn(v10, v11);
                    __nv_bfloat162 l = __floats2bfloat162_rn(
                        v10 - __bfloat162float(__low2bfloat16(h)),
                        v11 - __bfloat162float(__high2bfloat16(h)));
                    *(__nv_bfloat162*)(OutHi + (size_t)r1 * D + cc) = h;
                    *(__nv_bfloat162*)(OutLo + (size_t)r1 * D + cc) = l;
                }
            } else {
                if (r0 < M) *(float2*)(OutF + (size_t)r0 * D + cc) = make_float2(v00, v01);
                if (r1 < M) *(float2*)(OutF + (size_t)r1 * D + cc) = make_float2(v10, v11);
            }
        }
    }
}

// ======================= combine =======================
__global__ void __launch_bounds__(256) combine_kernel(float* __restrict__ out)
{
    int n = blockIdx.x;
    int s0 = g_slot_of[2 * n], s1 = g_slot_of[2 * n + 1];
    float g0 = g_gate0[n], g1 = g_gate1[n];
    float4* orow = (float4*)(out + (size_t)n * D);
    float4 v = orow[threadIdx.x];
    if (s0 >= 0) {
        float4 e = ((const float4*)(g_Oexp + (size_t)s0 * D))[threadIdx.x];
        v.x += g0 * e.x; v.y += g0 * e.y; v.z += g0 * e.z; v.w += g0 * e.w;
    }
    if (s1 >= 0) {
        float4 e = ((const float4*)(g_Oexp + (size_t)s1 * D))[threadIdx.x];
        v.x += g1 * e.x; v.y += g1 * e.y; v.z += g1 * e.z; v.w += g1 * e.w;
    }
    orow[threadIdx.x] = v;
}

// ======================= launch =======================
extern "C" void kernel_launch(void* const* d_in, const int* in_sizes, int n_in,
                              void* d_out, int out_size)
{
    const float* x     = (const float*)d_in[0];
    const float* noise = (const float*)d_in[1];
    const float* Wr    = (const float*)d_in[2];
    const float* br    = (const float*)d_in[3];
    const float* Wn    = (const float*)d_in[4];
    const float* bn    = (const float*)d_in[5];
    const float* W1    = (const float*)d_in[6];
    const float* b1    = (const float*)d_in[7];
    const float* W2    = (const float*)d_in[8];
    const float* b2    = (const float*)d_in[9];
    const float* Ws1   = (const float*)d_in[10];
    const float* bs1   = (const float*)d_in[11];
    const float* Ws2   = (const float*)d_in[12];
    const float* bs2   = (const float*)d_in[13];
    float* out = (float*)d_out;

    cudaFuncSetAttribute(moe_gemm<0>, cudaFuncAttributeMaxDynamicSharedMemorySize, GEMM_SMEM);
    cudaFuncSetAttribute(moe_gemm<1>, cudaFuncAttributeMaxDynamicSharedMemorySize, GEMM_SMEM);
    cudaFuncSetAttribute(moe_gemm<2>, cudaFuncAttributeMaxDynamicSharedMemorySize, GEMM_SMEM);
    cudaFuncSetAttribute(moe_gemm<3>, cudaFuncAttributeMaxDynamicSharedMemorySize, GEMM_SMEM);

    router_kernel<<<NTOK, 256>>>(x, noise, Wr, br, Wn, bn);
    init_slots<<<(NSLOTS + 255) / 256, 256>>>();
    scan_kernel<<<1, 1024>>>(out, out_size - 1);

    split_x_kernel<<<(NTOK * D) / 256, 256>>>(x);
    dim3 wsb(32, 8);
    wsplit_kernel<0><<<dim3(32, 32, 1),   wsb>>>(Ws1);
    wsplit_kernel<1><<<dim3(32, 32, 1),   wsb>>>(Ws2);
    wsplit_kernel<2><<<dim3(32, 32, EXP), wsb>>>(W1);
    wsplit_kernel<3><<<dim3(32, 32, EXP), wsb>>>(W2);

    // shared expert
    moe_gemm<0><<<dim3(D / 128, NTOK / 128, 1), 256, GEMM_SMEM>>>(bs1, nullptr, NTOK);
    moe_gemm<1><<<dim3(D / 128, NTOK / 128, 1), 256, GEMM_SMEM>>>(bs2, out, NTOK);

    // routed experts
    moe_gemm<2><<<dim3(D / 128, (CAP + 127) / 128, EXP), 256, GEMM_SMEM>>>(b1, nullptr, CAP);
    moe_gemm<3><<<dim3(D / 128, (CAP + 127) / 128, EXP), 256, GEMM_SMEM>>>(b2, nullptr, CAP);

    combine_kernel<<<NTOK, 256>>>(out);
}